// round 13
// baseline (speedup 1.0000x reference)
#include <cuda_runtime.h>
#include <stdint.h>

#define BB 16
#define NN 4096
#define DD 32
#define CC 64
#define KK 16
#define TS 128
#define TST 132       // padded row stride (floats)
#define NTILES (NN / TS)   // 32
#define THREADS 128
#define WARPS 4
#define QPC 256       // queries per CTA (2 per lane)
#define CAP 16        // per-lane stack depth per query

typedef unsigned long long u64;
typedef unsigned int u32;

// dynamic smem layout (bytes)
#define SZ_T     (DD * TST * 4)          // 16896 per buffer
#define SZ_RC    (TS * 4)                // 512 per buffer
#define OFF_T0   0
#define OFF_T1   SZ_T
#define OFF_RC0  (2 * SZ_T)
#define OFF_RC1  (2 * SZ_T + SZ_RC)
#define SZ_KBUF  (KK * 32 * 8)           // 4096
#define SZ_STK   (CAP * 32 * 8)          // 4096
#define SZ_WARP  (2 * SZ_KBUF + 2 * SZ_STK)   // 16384
#define OFF_W    (2 * SZ_T + 2 * SZ_RC)  // 34816
#define SMEM_TOTAL (OFF_W + WARPS * SZ_WARP)  // 100352

__device__ float g_norms[BB * NN];

__device__ __forceinline__ u64 pk2(float a, float b) {
    u64 r; asm("mov.b64 %0, {%1,%2};" : "=l"(r) : "f"(a), "f"(b)); return r;
}
__device__ __forceinline__ u64 fma2(u64 a, u64 b, u64 c) {
    u64 d; asm("fma.rn.f32x2 %0, %1, %2, %3;" : "=l"(d) : "l"(a), "l"(b), "l"(c));
    return d;
}
__device__ __forceinline__ void up2(u64 v, float& a, float& b) {
    asm("mov.b64 {%0,%1}, %2;" : "=f"(a), "=f"(b) : "l"(v));
}

// Balanced binary tree sum, XLA warp-shfl grouping (stride 16,8,4,2,1).
__device__ __forceinline__ float tree32(float t[32]) {
    #pragma unroll
    for (int off = 16; off >= 1; off >>= 1)
        #pragma unroll
        for (int i = 0; i < off; ++i)
            t[i] = __fadd_rn(t[i], t[i + off]);
    return t[0];
}

// Branch-free insert into ascending sorted k[0..15]; UINT64_MAX is a no-op.
__device__ __forceinline__ void ins16(u64 (&k)[KK], u64 nk) {
    #pragma unroll
    for (int s = KK - 1; s >= 1; --s) {
        u64 mn = (nk < k[s]) ? nk : k[s];
        k[s] = (k[s-1] > mn) ? k[s-1] : mn;
    }
    k[0] = (nk < k[0]) ? nk : k[0];
}

// threshold distance (float) from the worst kept key; sentinel -> +inf
__device__ __forceinline__ float thr_of(u64 wk) {
    u32 hi = (u32)(wk >> 32) ^ 0x80000000u;
    hi = hi < 0x7f800000u ? hi : 0x7f800000u;
    return __uint_as_float(hi);
}

__global__ void norms_kernel(const float* __restrict__ points) {
    int idx = blockIdx.x * blockDim.x + threadIdx.x;
    if (idx >= BB * NN) return;
    const float4* cp = (const float4*)(points + (size_t)idx * DD);
    float x[DD];
    #pragma unroll
    for (int j4 = 0; j4 < DD / 4; ++j4) {
        float4 v = __ldg(cp + j4);
        x[j4*4+0] = __fmul_rn(v.x, v.x);
        x[j4*4+1] = __fmul_rn(v.y, v.y);
        x[j4*4+2] = __fmul_rn(v.z, v.z);
        x[j4*4+3] = __fmul_rn(v.w, v.w);
    }
    g_norms[idx] = tree32(x);
}

// Drain lane's stack entries into its smem-resident sorted top-16.
__device__ __forceinline__ void drain(u64* stk, u64* kbuf, int lane,
                                      int& cnt, float& wq) {
    unsigned mx = __reduce_max_sync(0xffffffffu, (unsigned)cnt);
    if (mx == 0) return;
    u64 k[KK];
    #pragma unroll
    for (int i = 0; i < KK; ++i) k[i] = kbuf[i * 32 + lane];
    for (unsigned e = 0; e < mx; ++e) {
        u64 v = (e < (unsigned)cnt) ? stk[e * 32 + lane] : ~0ull;
        ins16(k, v);
    }
    #pragma unroll
    for (int i = 0; i < KK; ++i) kbuf[i * 32 + lane] = k[i];
    cnt = 0;
    wq = thr_of(k[KK - 1]);
}

// popc-prefix predicated stores of passing candidates (no serial chain, no vote)
__device__ __forceinline__ void store8(u64* stk, int lane, int& cnt,
                                       const float (&d)[8], int gi, u32 pm) {
    #pragma unroll
    for (int t = 0; t < 8; ++t) {
        if (pm & (1u << t)) {
            int pos = cnt + __popc(pm & ((1u << t) - 1u));
            u32 h = __float_as_uint(d[t]) | 0x80000000u;
            stk[pos * 32 + lane] = ((u64)h << 32) | (u32)(gi + t);
        }
    }
    cnt += __popc(pm);
}

__global__ __launch_bounds__(THREADS, 2)
void knn_select_kernel(const float* __restrict__ points,
                       const float* __restrict__ features,
                       float* __restrict__ out)
{
    extern __shared__ char smem_raw[];

    const int lane = threadIdx.x & 31;
    const int warp = threadIdx.x >> 5;
    const int b    = blockIdx.x >> 4;             // 16 CTAs per batch
    const int q0b  = (blockIdx.x & 15) * QPC;
    const int nq0  = q0b + warp * 32 + lane;
    const int nq1  = nq0 + 128;

    char* wbase = smem_raw + OFF_W + warp * SZ_WARP;
    u64* kbuf0 = (u64*)(wbase);
    u64* kbuf1 = (u64*)(wbase + SZ_KBUF);
    u64* stk0  = (u64*)(wbase + 2 * SZ_KBUF);
    u64* stk1  = (u64*)(wbase + 2 * SZ_KBUF + SZ_STK);

    const float* pb = points   + (size_t)b * NN * DD;
    const float* fb = features + (size_t)b * NN * CC;

    // tile loader: LDG tile -> transposed STS + rc, into buffer sel
    auto load_tile = [&](int tile, int sel) {
        float (*dst)[TST] = (float(*)[TST])(smem_raw + (sel ? OFF_T1 : OFF_T0));
        float* rcd = (float*)(smem_raw + (sel ? OFF_RC1 : OFF_RC0));
        const float4* src = (const float4*)(pb + (size_t)tile * TS * DD);
        #pragma unroll
        for (int it = 0; it < (TS * DD / 4) / THREADS; ++it) {   // 8
            int v  = threadIdx.x + it * THREADS;
            int c  = v >> 3;
            int j0 = (v & 7) << 2;
            float4 p4 = __ldg(src + v);
            dst[j0+0][c] = p4.x;
            dst[j0+1][c] = p4.y;
            dst[j0+2][c] = p4.z;
            dst[j0+3][c] = p4.w;
        }
        if (threadIdx.x < TS / 4)
            *(float4*)&rcd[threadIdx.x * 4] =
                *(const float4*)&g_norms[b * NN + tile * TS + threadIdx.x * 4];
    };

    // init smem k-lists to sentinel
    #pragma unroll
    for (int i = 0; i < KK; ++i) {
        kbuf0[i * 32 + lane] = ~0ull;
        kbuf1[i * 32 + lane] = ~0ull;
    }

    // ---- both query points: packed u64 duplicates + rq (tree32, ref order) ----
    u64 qd0[DD], qd1[DD];
    float rq0, rq1;
    {
        float x[DD];
        const float4* qp = (const float4*)(pb + (size_t)nq0 * DD);
        #pragma unroll
        for (int j4 = 0; j4 < DD / 4; ++j4) {
            float4 v = __ldg(qp + j4);
            qd0[j4*4+0] = pk2(v.x, v.x); qd0[j4*4+1] = pk2(v.y, v.y);
            qd0[j4*4+2] = pk2(v.z, v.z); qd0[j4*4+3] = pk2(v.w, v.w);
            x[j4*4+0] = __fmul_rn(v.x, v.x); x[j4*4+1] = __fmul_rn(v.y, v.y);
            x[j4*4+2] = __fmul_rn(v.z, v.z); x[j4*4+3] = __fmul_rn(v.w, v.w);
        }
        rq0 = tree32(x);
        qp = (const float4*)(pb + (size_t)nq1 * DD);
        #pragma unroll
        for (int j4 = 0; j4 < DD / 4; ++j4) {
            float4 v = __ldg(qp + j4);
            qd1[j4*4+0] = pk2(v.x, v.x); qd1[j4*4+1] = pk2(v.y, v.y);
            qd1[j4*4+2] = pk2(v.z, v.z); qd1[j4*4+3] = pk2(v.w, v.w);
            x[j4*4+0] = __fmul_rn(v.x, v.x); x[j4*4+1] = __fmul_rn(v.y, v.y);
            x[j4*4+2] = __fmul_rn(v.z, v.z); x[j4*4+3] = __fmul_rn(v.w, v.w);
        }
        rq1 = tree32(x);
    }

    float wq0 = __int_as_float(0x7f800000), wq1 = __int_as_float(0x7f800000);
    int cnt0 = 0, cnt1 = 0;

    const unsigned FULL = 0xffffffffu;

    // preload tile 0 into buffer 0
    load_tile(0, 0);
    __syncthreads();

    for (int tile = 0; tile < NTILES; ++tile) {
        const int cur = tile & 1;
        // prefetch next tile into the other buffer (overlaps with compute below)
        if (tile + 1 < NTILES) load_tile(tile + 1, cur ^ 1);

        float (*s_t)[TST] = (float(*)[TST])(smem_raw + (cur ? OFF_T1 : OFF_T0));
        float* s_rc = (float*)(smem_raw + (cur ? OFF_RC1 : OFF_RC0));

        #pragma unroll 1
        for (int c8 = 0; c8 < TS; c8 += 8) {
            // ---- 8 candidates x 2 queries: 8 packed FMA chains (ascending j) ----
            u64 acc[8];
            #pragma unroll
            for (int i = 0; i < 8; ++i) acc[i] = 0ull;
            #pragma unroll
            for (int j = 0; j < DD; ++j) {
                const ulonglong2* row = (const ulonglong2*)&s_t[j][c8];
                ulonglong2 pA = row[0], pB = row[1];
                acc[0] = fma2(qd0[j], pA.x, acc[0]);
                acc[1] = fma2(qd0[j], pA.y, acc[1]);
                acc[2] = fma2(qd0[j], pB.x, acc[2]);
                acc[3] = fma2(qd0[j], pB.y, acc[3]);
                acc[4] = fma2(qd1[j], pA.x, acc[4]);
                acc[5] = fma2(qd1[j], pA.y, acc[5]);
                acc[6] = fma2(qd1[j], pB.x, acc[6]);
                acc[7] = fma2(qd1[j], pB.y, acc[7]);
            }
            const int gi = tile * TS + c8;
            float rc[8];
            {
                float4 r0 = *(const float4*)&s_rc[c8];
                float4 r1 = *(const float4*)&s_rc[c8 + 4];
                rc[0]=r0.x; rc[1]=r0.y; rc[2]=r0.z; rc[3]=r0.w;
                rc[4]=r1.x; rc[5]=r1.y; rc[6]=r1.z; rc[7]=r1.w;
            }

            // D = fl(fl(rq - 2m) + rc); FFMA(-2,m,rq) == fl(rq - fl(2m)) bitwise
            float d0[8], d1[8];
            #pragma unroll
            for (int p = 0; p < 4; ++p) {
                float a, b_;
                up2(acc[p], a, b_);
                d0[2*p]   = __fadd_rn(__fmaf_rn(-2.f, a,  rq0), rc[2*p]);
                d0[2*p+1] = __fadd_rn(__fmaf_rn(-2.f, b_, rq0), rc[2*p+1]);
                up2(acc[4 + p], a, b_);
                d1[2*p]   = __fadd_rn(__fmaf_rn(-2.f, a,  rq1), rc[2*p]);
                d1[2*p+1] = __fadd_rn(__fmaf_rn(-2.f, b_, rq1), rc[2*p+1]);
            }

            // pass masks (self excluded by identity), ONE vote for the block
            u32 pm0 = 0, pm1 = 0;
            #pragma unroll
            for (int t = 0; t < 8; ++t) {
                pm0 |= (d0[t] <= wq0) ? (1u << t) : 0u;
                pm1 |= (d1[t] <= wq1) ? (1u << t) : 0u;
            }
            u32 df0 = (u32)(nq0 - gi);
            u32 df1 = (u32)(nq1 - gi);
            if (df0 < 8u) pm0 &= ~(1u << df0);
            if (df1 < 8u) pm1 &= ~(1u << df1);

            if (__any_sync(FULL, pm0 | pm1)) {
                store8(stk0, lane, cnt0, d0, gi, pm0);
                store8(stk1, lane, cnt1, d1, gi, pm1);
                int cmx = (cnt0 > cnt1) ? cnt0 : cnt1;
                if (__any_sync(FULL, cmx > CAP - 8)) {
                    drain(stk0, kbuf0, lane, cnt0, wq0);
                    drain(stk1, kbuf1, lane, cnt1, wq1);
                }
            }
        }
        __syncthreads();   // compute on cur done everywhere; next tile's stores done
    }

    // final drains: kbuf holds sorted top-16 by (dist, idx) = reference order
    drain(stk0, kbuf0, lane, cnt0, wq0);
    drain(stk1, kbuf1, lane, cnt1, wq1);
    __syncwarp();

    // publish indices into stack region (now dead): si[qq][kk], qq in [0,64)
    int* si = (int*)stk0;
    #pragma unroll
    for (int kk = 0; kk < KK; ++kk) {
        si[lane * KK + kk]        = (int)(u32)kbuf0[kk * 32 + lane];
        si[(32 + lane) * KK + kk] = (int)(u32)kbuf1[kk * 32 + lane];
    }
    __syncwarp();

    // ---- gather + write: 2 contiguous channels per lane, 64-bit accesses ----
    const int l2 = lane * 2;
    for (int qq = 0; qq < 64; ++qq) {
        int n = q0b + ((qq >> 5) << 7) + warp * 32 + (qq & 31);
        float2 c = *(const float2*)(fb + (size_t)n * CC + l2);
        float* ob = out + (size_t)(b * NN + n) * KK * (2 * CC);
        #pragma unroll
        for (int kk = 0; kk < KK; ++kk) {
            int nbv = si[qq * KK + kk];
            float2 g = *(const float2*)(fb + (size_t)nbv * CC + l2);
            float* orow = ob + kk * (2 * CC);
            __stcs((float2*)(orow + l2), g);
            __stcs((float2*)(orow + 64 + l2), make_float2(g.x - c.x, g.y - c.y));
        }
    }
}

extern "C" void kernel_launch(void* const* d_in, const int* in_sizes, int n_in,
                              void* d_out, int out_size) {
    const float* points   = (const float*)d_in[0];
    const float* features = (const float*)d_in[1];
    float* out = (float*)d_out;
    (void)in_sizes; (void)n_in; (void)out_size;
    cudaFuncSetAttribute(knn_select_kernel,
                         cudaFuncAttributeMaxDynamicSharedMemorySize, SMEM_TOTAL);
    norms_kernel<<<(BB * NN + 255) / 256, 256>>>(points);
    knn_select_kernel<<<BB * (NN / QPC), THREADS, SMEM_TOTAL>>>(points, features, out);
}

// round 14
// speedup vs baseline: 1.0078x; 1.0078x over previous
#include <cuda_runtime.h>
#include <stdint.h>

#define BB 16
#define NN 4096
#define DD 32
#define CC 64
#define KK 16
#define TS 256
#define TST 260       // padded row stride (floats); 1040B, 16B-aligned
#define NTILES (NN / TS)
#define THREADS 128
#define WARPS 4
#define QPC 256       // queries per CTA (2 per lane)
#define CAP 22        // per-lane stack depth per query

typedef unsigned long long u64;
typedef unsigned int u32;

// dynamic smem layout (bytes)
#define SZ_T     (DD * TST * 4)          // 33280
#define SZ_RC    (TS * 4)                // 1024
#define SZ_KBUF  (KK * 32 * 8)           // 4096
#define SZ_STK   (CAP * 32 * 8)          // 5632
#define SZ_WARP  (2 * SZ_KBUF + 2 * SZ_STK)   // 19456
#define OFF_RC   SZ_T
#define OFF_W    (SZ_T + SZ_RC)
#define SMEM_TOTAL (OFF_W + WARPS * SZ_WARP)  // 112128

__device__ float g_norms[BB * NN];

__device__ __forceinline__ u64 pk2(float a, float b) {
    u64 r; asm("mov.b64 %0, {%1,%2};" : "=l"(r) : "f"(a), "f"(b)); return r;
}
__device__ __forceinline__ u64 fma2(u64 a, u64 b, u64 c) {
    u64 d; asm("fma.rn.f32x2 %0, %1, %2, %3;" : "=l"(d) : "l"(a), "l"(b), "l"(c));
    return d;
}
__device__ __forceinline__ u64 add2(u64 a, u64 b) {
    u64 d; asm("add.rn.f32x2 %0, %1, %2;" : "=l"(d) : "l"(a), "l"(b));
    return d;
}
__device__ __forceinline__ void up2(u64 v, float& a, float& b) {
    asm("mov.b64 {%0,%1}, %2;" : "=f"(a), "=f"(b) : "l"(v));
}

// Balanced binary tree sum, XLA warp-shfl grouping (stride 16,8,4,2,1).
__device__ __forceinline__ float tree32(float t[32]) {
    #pragma unroll
    for (int off = 16; off >= 1; off >>= 1)
        #pragma unroll
        for (int i = 0; i < off; ++i)
            t[i] = __fadd_rn(t[i], t[i + off]);
    return t[0];
}

// Branch-free insert into ascending sorted k[0..15]; UINT64_MAX is a no-op.
__device__ __forceinline__ void ins16(u64 (&k)[KK], u64 nk) {
    #pragma unroll
    for (int s = KK - 1; s >= 1; --s) {
        u64 mn = (nk < k[s]) ? nk : k[s];
        k[s] = (k[s-1] > mn) ? k[s-1] : mn;
    }
    k[0] = (nk < k[0]) ? nk : k[0];
}

// threshold distance (float) from the worst kept key; sentinel -> +inf
__device__ __forceinline__ float thr_of(u64 wk) {
    u32 hi = (u32)(wk >> 32) ^ 0x80000000u;
    hi = hi < 0x7f800000u ? hi : 0x7f800000u;
    return __uint_as_float(hi);
}

__global__ void norms_kernel(const float* __restrict__ points) {
    int idx = blockIdx.x * blockDim.x + threadIdx.x;
    if (idx >= BB * NN) return;
    const float4* cp = (const float4*)(points + (size_t)idx * DD);
    float x[DD];
    #pragma unroll
    for (int j4 = 0; j4 < DD / 4; ++j4) {
        float4 v = __ldg(cp + j4);
        x[j4*4+0] = __fmul_rn(v.x, v.x);
        x[j4*4+1] = __fmul_rn(v.y, v.y);
        x[j4*4+2] = __fmul_rn(v.z, v.z);
        x[j4*4+3] = __fmul_rn(v.w, v.w);
    }
    g_norms[idx] = tree32(x);
}

// Drain lane's stack entries into its smem-resident sorted top-16.
__device__ __forceinline__ void drain(u64* stk, u64* kbuf, int lane,
                                      int& cnt, float& wq) {
    unsigned mx = __reduce_max_sync(0xffffffffu, (unsigned)cnt);
    if (mx == 0) return;
    u64 k[KK];
    #pragma unroll
    for (int i = 0; i < KK; ++i) k[i] = kbuf[i * 32 + lane];
    for (unsigned e = 0; e < mx; ++e) {
        u64 v = (e < (unsigned)cnt) ? stk[e * 32 + lane] : ~0ull;
        ins16(k, v);
    }
    #pragma unroll
    for (int i = 0; i < KK; ++i) kbuf[i * 32 + lane] = k[i];
    cnt = 0;
    wq = thr_of(k[KK - 1]);
}

// popc-prefix predicated stores of passing candidates (no serial chain, no vote)
__device__ __forceinline__ void store8(u64* stk, int lane, int& cnt,
                                       const float (&d)[8], int gi, u32 pm) {
    #pragma unroll
    for (int t = 0; t < 8; ++t) {
        if (pm & (1u << t)) {
            int pos = cnt + __popc(pm & ((1u << t) - 1u));
            u32 h = __float_as_uint(d[t]) | 0x80000000u;
            stk[pos * 32 + lane] = ((u64)h << 32) | (u32)(gi + t);
        }
    }
    cnt += __popc(pm);
}

__global__ __launch_bounds__(THREADS, 2)
void knn_select_kernel(const float* __restrict__ points,
                       const float* __restrict__ features,
                       float* __restrict__ out)
{
    extern __shared__ char smem_raw[];
    float (*s_t)[TST] = (float(*)[TST])smem_raw;
    float* s_rc = (float*)(smem_raw + OFF_RC);

    const int lane = threadIdx.x & 31;
    const int warp = threadIdx.x >> 5;
    const int b    = blockIdx.x >> 4;             // 16 CTAs per batch
    const int q0b  = (blockIdx.x & 15) * QPC;
    const int nq0  = q0b + warp * 32 + lane;
    const int nq1  = nq0 + 128;

    char* wbase = smem_raw + OFF_W + warp * SZ_WARP;
    u64* kbuf0 = (u64*)(wbase);
    u64* kbuf1 = (u64*)(wbase + SZ_KBUF);
    u64* stk0  = (u64*)(wbase + 2 * SZ_KBUF);
    u64* stk1  = (u64*)(wbase + 2 * SZ_KBUF + SZ_STK);

    const float* pb = points   + (size_t)b * NN * DD;
    const float* fb = features + (size_t)b * NN * CC;

    // init smem k-lists to sentinel
    #pragma unroll
    for (int i = 0; i < KK; ++i) {
        kbuf0[i * 32 + lane] = ~0ull;
        kbuf1[i * 32 + lane] = ~0ull;
    }

    // ---- both query points: packed u64 duplicates + rq (tree32, ref order) ----
    u64 qd0[DD], qd1[DD];
    float rq0, rq1;
    {
        float x[DD];
        const float4* qp = (const float4*)(pb + (size_t)nq0 * DD);
        #pragma unroll
        for (int j4 = 0; j4 < DD / 4; ++j4) {
            float4 v = __ldg(qp + j4);
            qd0[j4*4+0] = pk2(v.x, v.x); qd0[j4*4+1] = pk2(v.y, v.y);
            qd0[j4*4+2] = pk2(v.z, v.z); qd0[j4*4+3] = pk2(v.w, v.w);
            x[j4*4+0] = __fmul_rn(v.x, v.x); x[j4*4+1] = __fmul_rn(v.y, v.y);
            x[j4*4+2] = __fmul_rn(v.z, v.z); x[j4*4+3] = __fmul_rn(v.w, v.w);
        }
        rq0 = tree32(x);
        qp = (const float4*)(pb + (size_t)nq1 * DD);
        #pragma unroll
        for (int j4 = 0; j4 < DD / 4; ++j4) {
            float4 v = __ldg(qp + j4);
            qd1[j4*4+0] = pk2(v.x, v.x); qd1[j4*4+1] = pk2(v.y, v.y);
            qd1[j4*4+2] = pk2(v.z, v.z); qd1[j4*4+3] = pk2(v.w, v.w);
            x[j4*4+0] = __fmul_rn(v.x, v.x); x[j4*4+1] = __fmul_rn(v.y, v.y);
            x[j4*4+2] = __fmul_rn(v.z, v.z); x[j4*4+3] = __fmul_rn(v.w, v.w);
        }
        rq1 = tree32(x);
    }
    const u64 rqp0 = pk2(rq0, rq0);
    const u64 rqp1 = pk2(rq1, rq1);
    const u64 n2p  = pk2(-2.f, -2.f);

    float wq0 = __int_as_float(0x7f800000), wq1 = __int_as_float(0x7f800000);
    int cnt0 = 0, cnt1 = 0;

    const unsigned FULL = 0xffffffffu;

    for (int tile = 0; tile < NTILES; ++tile) {
        __syncthreads();
        {
            const float4* src = (const float4*)(pb + (size_t)tile * TS * DD);
            #pragma unroll
            for (int it = 0; it < (TS * DD / 4) / THREADS; ++it) {   // 16
                int v  = threadIdx.x + it * THREADS;
                int c  = v >> 3;
                int j0 = (v & 7) << 2;
                float4 p4 = src[v];
                s_t[j0+0][c] = p4.x;
                s_t[j0+1][c] = p4.y;
                s_t[j0+2][c] = p4.z;
                s_t[j0+3][c] = p4.w;
            }
            if (threadIdx.x < TS / 4)
                *(float4*)&s_rc[threadIdx.x * 4] =
                    *(const float4*)&g_norms[b * NN + tile * TS + threadIdx.x * 4];
        }
        __syncthreads();

        #pragma unroll 2
        for (int c8 = 0; c8 < TS; c8 += 8) {
            // ---- 8 candidates x 2 queries: 8 packed FMA chains (ascending j) ----
            u64 acc[8];
            #pragma unroll
            for (int i = 0; i < 8; ++i) acc[i] = 0ull;
            #pragma unroll
            for (int j = 0; j < DD; ++j) {
                const ulonglong2* row = (const ulonglong2*)&s_t[j][c8];
                ulonglong2 pA = row[0], pB = row[1];
                acc[0] = fma2(qd0[j], pA.x, acc[0]);
                acc[1] = fma2(qd0[j], pA.y, acc[1]);
                acc[2] = fma2(qd0[j], pB.x, acc[2]);
                acc[3] = fma2(qd0[j], pB.y, acc[3]);
                acc[4] = fma2(qd1[j], pA.x, acc[4]);
                acc[5] = fma2(qd1[j], pA.y, acc[5]);
                acc[6] = fma2(qd1[j], pB.x, acc[6]);
                acc[7] = fma2(qd1[j], pB.y, acc[7]);
            }
            const int gi = tile * TS + c8;

            // rc pairs (u64) straight from smem, 2x LDS.128
            const ulonglong2* rcp = (const ulonglong2*)&s_rc[c8];
            ulonglong2 rcA = rcp[0], rcB = rcp[1];

            // D = fl(fl(rq - 2m) + rc), computed pairwise in f32x2:
            // fma2(acc, -2, rq) == FFMA(-2,m,rq) per half; add2 == FADD per half
            u64 dp0[4], dp1[4];
            dp0[0] = add2(fma2(acc[0], n2p, rqp0), rcA.x);
            dp0[1] = add2(fma2(acc[1], n2p, rqp0), rcA.y);
            dp0[2] = add2(fma2(acc[2], n2p, rqp0), rcB.x);
            dp0[3] = add2(fma2(acc[3], n2p, rqp0), rcB.y);
            dp1[0] = add2(fma2(acc[4], n2p, rqp1), rcA.x);
            dp1[1] = add2(fma2(acc[5], n2p, rqp1), rcA.y);
            dp1[2] = add2(fma2(acc[6], n2p, rqp1), rcB.x);
            dp1[3] = add2(fma2(acc[7], n2p, rqp1), rcB.y);

            float d0[8], d1[8];
            #pragma unroll
            for (int p = 0; p < 4; ++p) {
                up2(dp0[p], d0[2*p], d0[2*p+1]);
                up2(dp1[p], d1[2*p], d1[2*p+1]);
            }

            // pass masks (self excluded by identity), ONE vote for the block
            u32 pm0 = 0, pm1 = 0;
            #pragma unroll
            for (int t = 0; t < 8; ++t) {
                pm0 |= (d0[t] <= wq0) ? (1u << t) : 0u;
                pm1 |= (d1[t] <= wq1) ? (1u << t) : 0u;
            }
            u32 df0 = (u32)(nq0 - gi);
            u32 df1 = (u32)(nq1 - gi);
            if (df0 < 8u) pm0 &= ~(1u << df0);
            if (df1 < 8u) pm1 &= ~(1u << df1);

            if (__any_sync(FULL, pm0 | pm1)) {
                store8(stk0, lane, cnt0, d0, gi, pm0);
                store8(stk1, lane, cnt1, d1, gi, pm1);
                int cmx = (cnt0 > cnt1) ? cnt0 : cnt1;
                if (__any_sync(FULL, cmx > CAP - 8)) {
                    drain(stk0, kbuf0, lane, cnt0, wq0);
                    drain(stk1, kbuf1, lane, cnt1, wq1);
                }
            }
        }
    }

    // final drains: kbuf holds sorted top-16 by (dist, idx) = reference order
    drain(stk0, kbuf0, lane, cnt0, wq0);
    drain(stk1, kbuf1, lane, cnt1, wq1);
    __syncwarp();

    // publish indices into stack region (now dead): si[qq][kk], qq in [0,64)
    int* si = (int*)stk0;
    #pragma unroll
    for (int kk = 0; kk < KK; ++kk) {
        si[lane * KK + kk]        = (int)(u32)kbuf0[kk * 32 + lane];
        si[(32 + lane) * KK + kk] = (int)(u32)kbuf1[kk * 32 + lane];
    }
    __syncwarp();

    // ---- gather + write: 2 contiguous channels per lane, 64-bit accesses ----
    const int l2 = lane * 2;
    for (int qq = 0; qq < 64; ++qq) {
        int n = q0b + ((qq >> 5) << 7) + warp * 32 + (qq & 31);
        float2 c = *(const float2*)(fb + (size_t)n * CC + l2);
        float* ob = out + (size_t)(b * NN + n) * KK * (2 * CC);
        #pragma unroll
        for (int kk = 0; kk < KK; ++kk) {
            int nbv = si[qq * KK + kk];
            float2 g = *(const float2*)(fb + (size_t)nbv * CC + l2);
            float* orow = ob + kk * (2 * CC);
            __stcs((float2*)(orow + l2), g);
            __stcs((float2*)(orow + 64 + l2), make_float2(g.x - c.x, g.y - c.y));
        }
    }
}

extern "C" void kernel_launch(void* const* d_in, const int* in_sizes, int n_in,
                              void* d_out, int out_size) {
    const float* points   = (const float*)d_in[0];
    const float* features = (const float*)d_in[1];
    float* out = (float*)d_out;
    (void)in_sizes; (void)n_in; (void)out_size;
    cudaFuncSetAttribute(knn_select_kernel,
                         cudaFuncAttributeMaxDynamicSharedMemorySize, SMEM_TOTAL);
    norms_kernel<<<(BB * NN + 255) / 256, 256>>>(points);
    knn_select_kernel<<<BB * (NN / QPC), THREADS, SMEM_TOTAL>>>(points, features, out);
}

// round 15
// speedup vs baseline: 1.0326x; 1.0246x over previous
#include <cuda_runtime.h>
#include <stdint.h>

#define BB 16
#define NN 4096
#define DD 32
#define CC 64
#define KK 16
#define TSW 64         // candidates per warp-private tile
#define TSWP 68        // padded row stride (floats)
#define NTILES (NN / TSW)   // 64
#define THREADS 128
#define WARPS 4
#define QPC 256        // queries per CTA (2 per lane)
#define CAP 16         // per-lane stack depth per query

typedef unsigned long long u64;
typedef unsigned int u32;

// dynamic smem layout (bytes) — everything per-warp, no CTA sharing
#define SZ_T     (DD * TSWP * 4)         // 8704
#define SZ_RC    (TSW * 4)               // 256
#define SZ_KBUF  (KK * 32 * 8)           // 4096
#define SZ_STK   (CAP * 32 * 8)          // 4096
#define SZ_WARP  (SZ_T + SZ_RC + 2 * SZ_KBUF + 2 * SZ_STK)  // 25344
#define SMEM_TOTAL (WARPS * SZ_WARP)     // 101376

__device__ float g_norms[BB * NN];

__device__ __forceinline__ u64 pk2(float a, float b) {
    u64 r; asm("mov.b64 %0, {%1,%2};" : "=l"(r) : "f"(a), "f"(b)); return r;
}
__device__ __forceinline__ u64 fma2(u64 a, u64 b, u64 c) {
    u64 d; asm("fma.rn.f32x2 %0, %1, %2, %3;" : "=l"(d) : "l"(a), "l"(b), "l"(c));
    return d;
}
__device__ __forceinline__ void up2(u64 v, float& a, float& b) {
    asm("mov.b64 {%0,%1}, %2;" : "=f"(a), "=f"(b) : "l"(v));
}

// Balanced binary tree sum, XLA warp-shfl grouping (stride 16,8,4,2,1).
__device__ __forceinline__ float tree32(float t[32]) {
    #pragma unroll
    for (int off = 16; off >= 1; off >>= 1)
        #pragma unroll
        for (int i = 0; i < off; ++i)
            t[i] = __fadd_rn(t[i], t[i + off]);
    return t[0];
}

// Branch-free insert into ascending sorted k[0..15]; UINT64_MAX is a no-op.
__device__ __forceinline__ void ins16(u64 (&k)[KK], u64 nk) {
    #pragma unroll
    for (int s = KK - 1; s >= 1; --s) {
        u64 mn = (nk < k[s]) ? nk : k[s];
        k[s] = (k[s-1] > mn) ? k[s-1] : mn;
    }
    k[0] = (nk < k[0]) ? nk : k[0];
}

// threshold distance (float) from the worst kept key; sentinel -> +inf
__device__ __forceinline__ float thr_of(u64 wk) {
    u32 hi = (u32)(wk >> 32) ^ 0x80000000u;
    hi = hi < 0x7f800000u ? hi : 0x7f800000u;
    return __uint_as_float(hi);
}

__global__ void norms_kernel(const float* __restrict__ points) {
    int idx = blockIdx.x * blockDim.x + threadIdx.x;
    if (idx >= BB * NN) return;
    const float4* cp = (const float4*)(points + (size_t)idx * DD);
    float x[DD];
    #pragma unroll
    for (int j4 = 0; j4 < DD / 4; ++j4) {
        float4 v = __ldg(cp + j4);
        x[j4*4+0] = __fmul_rn(v.x, v.x);
        x[j4*4+1] = __fmul_rn(v.y, v.y);
        x[j4*4+2] = __fmul_rn(v.z, v.z);
        x[j4*4+3] = __fmul_rn(v.w, v.w);
    }
    g_norms[idx] = tree32(x);
}

// Drain lane's stack entries into its smem-resident sorted top-16.
__device__ __forceinline__ void drain(u64* stk, u64* kbuf, int lane,
                                      int& cnt, float& wq) {
    unsigned mx = __reduce_max_sync(0xffffffffu, (unsigned)cnt);
    if (mx == 0) return;
    u64 k[KK];
    #pragma unroll
    for (int i = 0; i < KK; ++i) k[i] = kbuf[i * 32 + lane];
    for (unsigned e = 0; e < mx; ++e) {
        u64 v = (e < (unsigned)cnt) ? stk[e * 32 + lane] : ~0ull;
        ins16(k, v);
    }
    #pragma unroll
    for (int i = 0; i < KK; ++i) kbuf[i * 32 + lane] = k[i];
    cnt = 0;
    wq = thr_of(k[KK - 1]);
}

// popc-prefix predicated push of up-to-8 passing candidates (no serial chain)
__device__ __forceinline__ void push8(u64* stk, int lane, int& cnt,
                                      const float (&d)[8], int gi, float wq,
                                      int nq, u64* kbuf, float& wqr) {
    const unsigned FULL = 0xffffffffu;
    u32 pm = 0;
    #pragma unroll
    for (int t = 0; t < 8; ++t) pm |= (d[t] <= wq) ? (1u << t) : 0u;
    u32 diff = (u32)(nq - gi);
    if (diff < 8u) pm &= ~(1u << diff);        // exclude self by identity
    if (__any_sync(FULL, pm)) {
        #pragma unroll
        for (int t = 0; t < 8; ++t) {
            if (pm & (1u << t)) {
                int pos = cnt + __popc(pm & ((1u << t) - 1u));
                u32 h = __float_as_uint(d[t]) | 0x80000000u;
                stk[pos * 32 + lane] = ((u64)h << 32) | (u32)(gi + t);
            }
        }
        cnt += __popc(pm);
        if (__any_sync(FULL, cnt > CAP - 8))
            drain(stk, kbuf, lane, cnt, wqr);
    }
}

__global__ __launch_bounds__(THREADS, 2)
void knn_select_kernel(const float* __restrict__ points,
                       const float* __restrict__ features,
                       float* __restrict__ out)
{
    extern __shared__ char smem_raw[];

    const int lane = threadIdx.x & 31;
    const int warp = threadIdx.x >> 5;
    const int b    = blockIdx.x >> 4;             // 16 CTAs per batch
    const int q0b  = (blockIdx.x & 15) * QPC;
    const int nq0  = q0b + warp * 32 + lane;
    const int nq1  = nq0 + 128;

    char* wbase = smem_raw + warp * SZ_WARP;      // this warp's private arena
    float (*s_t)[TSWP] = (float(*)[TSWP])wbase;
    float* s_rc = (float*)(wbase + SZ_T);
    u64* kbuf0  = (u64*)(wbase + SZ_T + SZ_RC);
    u64* kbuf1  = (u64*)(wbase + SZ_T + SZ_RC + SZ_KBUF);
    u64* stk0   = (u64*)(wbase + SZ_T + SZ_RC + 2 * SZ_KBUF);
    u64* stk1   = (u64*)(wbase + SZ_T + SZ_RC + 2 * SZ_KBUF + SZ_STK);

    const float* pb = points   + (size_t)b * NN * DD;
    const float* fb = features + (size_t)b * NN * CC;

    // init smem k-lists to sentinel
    #pragma unroll
    for (int i = 0; i < KK; ++i) {
        kbuf0[i * 32 + lane] = ~0ull;
        kbuf1[i * 32 + lane] = ~0ull;
    }

    // ---- both query points: packed u64 duplicates + rq (tree32, ref order) ----
    u64 qd0[DD], qd1[DD];
    float rq0, rq1;
    {
        float x[DD];
        const float4* qp = (const float4*)(pb + (size_t)nq0 * DD);
        #pragma unroll
        for (int j4 = 0; j4 < DD / 4; ++j4) {
            float4 v = __ldg(qp + j4);
            qd0[j4*4+0] = pk2(v.x, v.x); qd0[j4*4+1] = pk2(v.y, v.y);
            qd0[j4*4+2] = pk2(v.z, v.z); qd0[j4*4+3] = pk2(v.w, v.w);
            x[j4*4+0] = __fmul_rn(v.x, v.x); x[j4*4+1] = __fmul_rn(v.y, v.y);
            x[j4*4+2] = __fmul_rn(v.z, v.z); x[j4*4+3] = __fmul_rn(v.w, v.w);
        }
        rq0 = tree32(x);
        qp = (const float4*)(pb + (size_t)nq1 * DD);
        #pragma unroll
        for (int j4 = 0; j4 < DD / 4; ++j4) {
            float4 v = __ldg(qp + j4);
            qd1[j4*4+0] = pk2(v.x, v.x); qd1[j4*4+1] = pk2(v.y, v.y);
            qd1[j4*4+2] = pk2(v.z, v.z); qd1[j4*4+3] = pk2(v.w, v.w);
            x[j4*4+0] = __fmul_rn(v.x, v.x); x[j4*4+1] = __fmul_rn(v.y, v.y);
            x[j4*4+2] = __fmul_rn(v.z, v.z); x[j4*4+3] = __fmul_rn(v.w, v.w);
        }
        rq1 = tree32(x);
    }

    float wq0 = __int_as_float(0x7f800000), wq1 = __int_as_float(0x7f800000);
    int cnt0 = 0, cnt1 = 0;

    // ---- mainloop: warp-private tiles, NO __syncthreads anywhere ----
    for (int tile = 0; tile < NTILES; ++tile) {
        __syncwarp();
        {
            // 64 cands x 32 dims = 512 float4 -> 16 per lane, transposed STS
            const float4* src = (const float4*)(pb + (size_t)tile * TSW * DD);
            #pragma unroll
            for (int it = 0; it < (TSW * DD / 4) / 32; ++it) {   // 16
                int v  = lane + it * 32;
                int c  = v >> 3;
                int j0 = (v & 7) << 2;
                float4 p4 = __ldg(src + v);
                s_t[j0+0][c] = p4.x;
                s_t[j0+1][c] = p4.y;
                s_t[j0+2][c] = p4.z;
                s_t[j0+3][c] = p4.w;
            }
            *(float2*)&s_rc[lane * 2] =
                *(const float2*)&g_norms[b * NN + tile * TSW + lane * 2];
        }
        __syncwarp();

        #pragma unroll 1
        for (int c8 = 0; c8 < TSW; c8 += 8) {
            // ---- 8 candidates x 2 queries: 8 packed FMA chains (ascending j) ----
            u64 acc[8];
            #pragma unroll
            for (int i = 0; i < 8; ++i) acc[i] = 0ull;
            #pragma unroll
            for (int j = 0; j < DD; ++j) {
                const ulonglong2* row = (const ulonglong2*)&s_t[j][c8];
                ulonglong2 pA = row[0], pB = row[1];
                acc[0] = fma2(qd0[j], pA.x, acc[0]);
                acc[1] = fma2(qd0[j], pA.y, acc[1]);
                acc[2] = fma2(qd0[j], pB.x, acc[2]);
                acc[3] = fma2(qd0[j], pB.y, acc[3]);
                acc[4] = fma2(qd1[j], pA.x, acc[4]);
                acc[5] = fma2(qd1[j], pA.y, acc[5]);
                acc[6] = fma2(qd1[j], pB.x, acc[6]);
                acc[7] = fma2(qd1[j], pB.y, acc[7]);
            }
            const int gi = tile * TSW + c8;
            float rc[8];
            {
                float4 r0 = *(const float4*)&s_rc[c8];
                float4 r1 = *(const float4*)&s_rc[c8 + 4];
                rc[0]=r0.x; rc[1]=r0.y; rc[2]=r0.z; rc[3]=r0.w;
                rc[4]=r1.x; rc[5]=r1.y; rc[6]=r1.z; rc[7]=r1.w;
            }

            // D = fl(fl(rq - 2m) + rc); FFMA(-2,m,rq) == fl(rq - fl(2m)) bitwise
            float d0[8], d1[8];
            #pragma unroll
            for (int p = 0; p < 4; ++p) {
                float a, b_;
                up2(acc[p], a, b_);
                d0[2*p]   = __fadd_rn(__fmaf_rn(-2.f, a,  rq0), rc[2*p]);
                d0[2*p+1] = __fadd_rn(__fmaf_rn(-2.f, b_, rq0), rc[2*p+1]);
                up2(acc[4 + p], a, b_);
                d1[2*p]   = __fadd_rn(__fmaf_rn(-2.f, a,  rq1), rc[2*p]);
                d1[2*p+1] = __fadd_rn(__fmaf_rn(-2.f, b_, rq1), rc[2*p+1]);
            }

            push8(stk0, lane, cnt0, d0, gi, wq0, nq0, kbuf0, wq0);
            push8(stk1, lane, cnt1, d1, gi, wq1, nq1, kbuf1, wq1);
        }
    }

    // final drains: kbuf holds sorted top-16 by (dist, idx) = reference order
    drain(stk0, kbuf0, lane, cnt0, wq0);
    drain(stk1, kbuf1, lane, cnt1, wq1);
    __syncwarp();

    // publish indices into stack region (now dead): si[qq][kk], qq in [0,64)
    int* si = (int*)stk0;
    #pragma unroll
    for (int kk = 0; kk < KK; ++kk) {
        si[lane * KK + kk]        = (int)(u32)kbuf0[kk * 32 + lane];
        si[(32 + lane) * KK + kk] = (int)(u32)kbuf1[kk * 32 + lane];
    }
    __syncwarp();

    // ---- gather + write: 2 contiguous channels per lane, 64-bit accesses ----
    const int l2 = lane * 2;
    for (int qq = 0; qq < 64; ++qq) {
        int n = q0b + ((qq >> 5) << 7) + warp * 32 + (qq & 31);
        float2 c = *(const float2*)(fb + (size_t)n * CC + l2);
        float* ob = out + (size_t)(b * NN + n) * KK * (2 * CC);
        #pragma unroll
        for (int kk = 0; kk < KK; ++kk) {
            int nbv = si[qq * KK + kk];
            float2 g = *(const float2*)(fb + (size_t)nbv * CC + l2);
            float* orow = ob + kk * (2 * CC);
            __stcs((float2*)(orow + l2), g);
            __stcs((float2*)(orow + 64 + l2), make_float2(g.x - c.x, g.y - c.y));
        }
    }
}

extern "C" void kernel_launch(void* const* d_in, const int* in_sizes, int n_in,
                              void* d_out, int out_size) {
    const float* points   = (const float*)d_in[0];
    const float* features = (const float*)d_in[1];
    float* out = (float*)d_out;
    (void)in_sizes; (void)n_in; (void)out_size;
    cudaFuncSetAttribute(knn_select_kernel,
                         cudaFuncAttributeMaxDynamicSharedMemorySize, SMEM_TOTAL);
    norms_kernel<<<(BB * NN + 255) / 256, 256>>>(points);
    knn_select_kernel<<<BB * (NN / QPC), THREADS, SMEM_TOTAL>>>(points, features, out);
}